// round 13
// baseline (speedup 1.0000x reference)
#include <cuda_runtime.h>

// SPD identity-pad (p=1), warp-shift copy, occupancy-tuned:
//   x  : [BC=128][256][2304] fp32  (row = 576 float4, 16B-aligned)
//   out: [BC=128][258][2322] fp32
// Copy blocks: each warp owns 64 consecutive float4 of one input row.
// Aligned LDG.128 -> shuffle-shift by al in {1,3} floats -> aligned STG.128.
// Border blocks (prefix of grid): paint eye(3) on all border cells.

namespace {
constexpr int H        = 256;
constexpr int HO       = 258;
constexpr int ROW_IN   = 2304;
constexpr int ROW_IN4  = 576;
constexpr int ROW_OUT  = 2322;

constexpr int BPP      = 2 * ROW_OUT + H * 18;  // 9252 border floats / plane
constexpr int N_B      = 128 * BPP;             // 1,184,256
constexpr int BBLK     = N_B / 256;             // 4626 (exact)

constexpr int UNITS    = ROW_IN4 / 64;          // 9 warp-units per row
constexpr int NROWS    = 128 * H;               // 32768
constexpr int CBLK     = NROWS * UNITS / 8;     // 36864 copy blocks (exact)
constexpr unsigned FULL = 0xffffffffu;
}

__global__ void __launch_bounds__(256)
spd_fused_kernel(const float4* __restrict__ x4, float* __restrict__ out)
{
    const int bidx = blockIdx.x;

    if (bidx < BBLK) {
        // ---------- border path: eye(3) on all border cells ----------
        int idx = bidx * 256 + threadIdx.x;     // < N_B exactly
        int bc  = idx / BPP;
        int r   = idx - bc * BPP;
        int i, t;
        if (r < 2 * ROW_OUT) {                  // top / bottom full rows
            i = (r < ROW_OUT) ? 0 : (HO - 1);
            t = (r < ROW_OUT) ? r : (r - ROW_OUT);
        } else {                                // left / right strips (18/row)
            int r2 = r - 2 * ROW_OUT;
            int rr = r2 / 18;
            int s  = r2 - rr * 18;
            i = rr + 1;
            t = (s < 9) ? s : (ROW_IN + s);     // 0..8 or 2313..2321
        }
        int t9 = t % 9;                         // {0,4,8} -> 1
        out[(bc * HO + i) * ROW_OUT + t] = ((t9 % 4) == 0) ? 1.0f : 0.0f;
        return;
    }

    // ---------- copy path ----------
    const int w    = (bidx - BBLK) * 8 + (threadIdx.x >> 5);
    const int lane = threadIdx.x & 31;
    const int row  = w / UNITS;                 // 0..32767  (bc*256 + i)
    const int u    = w - row * UNITS;           // 0..8
    const int bc   = row >> 8;
    const int i    = row & 255;

    const int rb4 = row * ROW_IN4;
    const int b   = (bc * HO + i + 1) * ROW_OUT + 9;   // always odd
    const int al  = (4 - (b & 3)) & 3;                 // 1 or 3, warp-uniform
    const int a04 = (b + al) >> 2;

    const int c0 = u * 64 + lane;
    const int c1 = c0 + 32;
    const bool last = (c1 == ROW_IN4 - 1);      // only u==8, lane==31

    float4 v0 = __ldg(x4 + rb4 + c0);
    float4 v1 = __ldg(x4 + rb4 + c1);

    float4* out4 = reinterpret_cast<float4*>(out);

    if (al == 1) {
        // need in4[c+1].x only
        float n0x = __shfl_down_sync(FULL, v0.x, 1);
        float p0x = __shfl_sync(FULL, v1.x, 0);        // lane31's c0+1 = lane0's c1
        if (lane == 31) n0x = p0x;
        float n1x = __shfl_down_sync(FULL, v1.x, 1);
        if (lane == 31 && !last) n1x = __ldg((const float*)(x4 + rb4 + c1 + 1));
        out4[a04 + c0] = make_float4(v0.y, v0.z, v0.w, n0x);
        if (!last)
            out4[a04 + c1] = make_float4(v1.y, v1.z, v1.w, n1x);
    } else {
        // al == 3: need in4[c+1].{x,y,z}
        float n0x = __shfl_down_sync(FULL, v0.x, 1);
        float n0y = __shfl_down_sync(FULL, v0.y, 1);
        float n0z = __shfl_down_sync(FULL, v0.z, 1);
        float p0x = __shfl_sync(FULL, v1.x, 0);
        float p0y = __shfl_sync(FULL, v1.y, 0);
        float p0z = __shfl_sync(FULL, v1.z, 0);
        if (lane == 31) { n0x = p0x; n0y = p0y; n0z = p0z; }
        float n1x = __shfl_down_sync(FULL, v1.x, 1);
        float n1y = __shfl_down_sync(FULL, v1.y, 1);
        float n1z = __shfl_down_sync(FULL, v1.z, 1);
        if (lane == 31 && !last) {
            float4 nv = __ldg(x4 + rb4 + c1 + 1);
            n1x = nv.x; n1y = nv.y; n1z = nv.z;
        }
        out4[a04 + c0] = make_float4(v0.w, n0x, n0y, n0z);
        if (!last)
            out4[a04 + c1] = make_float4(v1.w, n1x, n1y, n1z);
    }

    // head: out[b .. b+al-1] = in[0 .. al-1]
    if (u == 0 && lane == 0) {
        out[b] = v0.x;
        if (al == 3) { out[b + 1] = v0.y; out[b + 2] = v0.z; }
    }
    // tail: out[b+al+2300 .. b+2303] = in[al+2300 .. 2303]; v1 = x4[575]
    if (last) {
        out[b + 2303] = v1.w;
        if (al == 1) { out[b + 2301] = v1.y; out[b + 2302] = v1.z; }
    }
}

extern "C" void kernel_launch(void* const* d_in, const int* in_sizes, int n_in,
                              void* d_out, int out_size)
{
    const float4* x4 = (const float4*)d_in[0];
    float* out = (float*)d_out;
    spd_fused_kernel<<<BBLK + CBLK, 256>>>(x4, out);   // 41490 blocks
}

// round 14
// speedup vs baseline: 1.0204x; 1.0204x over previous
#include <cuda_runtime.h>

// SPD identity-pad (p=1), warp-shift copy + streaming cache policy:
//   x  : [BC=128][256][2304] fp32  (row = 576 float4, 16B-aligned)
//   out: [BC=128][258][2322] fp32
// Identical structure to the verified fused kernel; all bulk loads/stores use
// evict-first streaming ops (__ldcs/__stcs) since there is zero data reuse.

namespace {
constexpr int H        = 256;
constexpr int HO       = 258;
constexpr int ROW_IN   = 2304;
constexpr int ROW_IN4  = 576;
constexpr int ROW_OUT  = 2322;

constexpr int BPP      = 2 * ROW_OUT + H * 18;  // 9252 border floats / plane
constexpr int N_B      = 128 * BPP;             // 1,184,256
constexpr int BBLK     = N_B / 256;             // 4626 (exact)

constexpr int UNITS    = ROW_IN4 / 64;          // 9 warp-units per row
constexpr int NROWS    = 128 * H;               // 32768
constexpr int CBLK     = NROWS * UNITS / 8;     // 36864 copy blocks (exact)
constexpr unsigned FULL = 0xffffffffu;
}

__global__ void __launch_bounds__(256)
spd_fused_cs_kernel(const float4* __restrict__ x4, float* __restrict__ out)
{
    const int bidx = blockIdx.x;

    if (bidx < BBLK) {
        // ---------- border path: eye(3) on all border cells ----------
        int idx = bidx * 256 + threadIdx.x;     // < N_B exactly
        int bc  = idx / BPP;
        int r   = idx - bc * BPP;
        int i, t;
        if (r < 2 * ROW_OUT) {                  // top / bottom full rows
            i = (r < ROW_OUT) ? 0 : (HO - 1);
            t = (r < ROW_OUT) ? r : (r - ROW_OUT);
        } else {                                // left / right strips (18/row)
            int r2 = r - 2 * ROW_OUT;
            int rr = r2 / 18;
            int s  = r2 - rr * 18;
            i = rr + 1;
            t = (s < 9) ? s : (ROW_IN + s);     // 0..8 or 2313..2321
        }
        int t9 = t % 9;                         // {0,4,8} -> 1
        __stcs(&out[(bc * HO + i) * ROW_OUT + t],
               ((t9 % 4) == 0) ? 1.0f : 0.0f);
        return;
    }

    // ---------- copy path ----------
    const int w    = (bidx - BBLK) * 8 + (threadIdx.x >> 5);
    const int lane = threadIdx.x & 31;
    const int row  = w / UNITS;                 // 0..32767  (bc*256 + i)
    const int u    = w - row * UNITS;           // 0..8
    const int bc   = row >> 8;
    const int i    = row & 255;

    const int rb4 = row * ROW_IN4;
    const int b   = (bc * HO + i + 1) * ROW_OUT + 9;   // always odd
    const int al  = (4 - (b & 3)) & 3;                 // 1 or 3, warp-uniform
    const int a04 = (b + al) >> 2;

    const int c0 = u * 64 + lane;
    const int c1 = c0 + 32;
    const bool last = (c1 == ROW_IN4 - 1);      // only u==8, lane==31

    float4 v0 = __ldcs(x4 + rb4 + c0);          // streaming, evict-first
    float4 v1 = __ldcs(x4 + rb4 + c1);

    float4* out4 = reinterpret_cast<float4*>(out);

    if (al == 1) {
        // need in4[c+1].x only
        float n0x = __shfl_down_sync(FULL, v0.x, 1);
        float p0x = __shfl_sync(FULL, v1.x, 0); // lane31's c0+1 = lane0's c1
        if (lane == 31) n0x = p0x;
        float n1x = __shfl_down_sync(FULL, v1.x, 1);
        if (lane == 31 && !last)
            n1x = __ldg((const float*)(x4 + rb4 + c1 + 1));
        __stcs(&out4[a04 + c0], make_float4(v0.y, v0.z, v0.w, n0x));
        if (!last)
            __stcs(&out4[a04 + c1], make_float4(v1.y, v1.z, v1.w, n1x));
    } else {
        // al == 3: need in4[c+1].{x,y,z}
        float n0x = __shfl_down_sync(FULL, v0.x, 1);
        float n0y = __shfl_down_sync(FULL, v0.y, 1);
        float n0z = __shfl_down_sync(FULL, v0.z, 1);
        float p0x = __shfl_sync(FULL, v1.x, 0);
        float p0y = __shfl_sync(FULL, v1.y, 0);
        float p0z = __shfl_sync(FULL, v1.z, 0);
        if (lane == 31) { n0x = p0x; n0y = p0y; n0z = p0z; }
        float n1x = __shfl_down_sync(FULL, v1.x, 1);
        float n1y = __shfl_down_sync(FULL, v1.y, 1);
        float n1z = __shfl_down_sync(FULL, v1.z, 1);
        if (lane == 31 && !last) {
            float4 nv = __ldg(x4 + rb4 + c1 + 1);
            n1x = nv.x; n1y = nv.y; n1z = nv.z;
        }
        __stcs(&out4[a04 + c0], make_float4(v0.w, n0x, n0y, n0z));
        if (!last)
            __stcs(&out4[a04 + c1], make_float4(v1.w, n1x, n1y, n1z));
    }

    // head: out[b .. b+al-1] = in[0 .. al-1]
    if (u == 0 && lane == 0) {
        __stcs(&out[b], v0.x);
        if (al == 3) { __stcs(&out[b + 1], v0.y); __stcs(&out[b + 2], v0.z); }
    }
    // tail: out[b+al+2300 .. b+2303] = in[al+2300 .. 2303]; v1 = x4[575]
    if (last) {
        __stcs(&out[b + 2303], v1.w);
        if (al == 1) { __stcs(&out[b + 2301], v1.y); __stcs(&out[b + 2302], v1.z); }
    }
}

extern "C" void kernel_launch(void* const* d_in, const int* in_sizes, int n_in,
                              void* d_out, int out_size)
{
    const float4* x4 = (const float4*)d_in[0];
    float* out = (float*)d_out;
    spd_fused_cs_kernel<<<BBLK + CBLK, 256>>>(x4, out);   // 41490 blocks
}